// round 2
// baseline (speedup 1.0000x reference)
#include <cuda_runtime.h>
#include <cuda_bf16.h>
#include <stdint.h>

// HabanaOptimizerSparseSgd:
//   weights_out[indices[i]] -= lr * gradients[i]   for i < valid_count
//   moments_out = moments (pass-through copy)
//
// Inputs (metadata order):
//   d_in[0] gradients  [N, 128] float32
//   d_in[1] weights    [V, 128] float32
//   d_in[2] moments    [V, 128] float32
//   d_in[3] indices    [N]      int64-declared, but JAX default x64-off makes
//                               it int32 on device -> auto-detect at runtime
//   d_in[4] learning_rate [1]   float32
// Output: concat(weights_out, moments_out) float32

#define EMB_D 128
#define VALID_COUNT_DEFAULT 200000

// 1 = indices are 8-byte, 0 = indices are 4-byte
__device__ int g_idx_is_i64;

__global__ void detect_index_width(const unsigned long long* __restrict__ idx_as_u64,
                                   int n_rows)
{
    // If the buffer really holds int64 indices (all < 2^31), every u64 word is
    // small. If it holds int32 indices, the high half of each u64 word is a
    // random index in [0, 1M) -> almost surely nonzero somewhere in 64 samples.
    int probe = n_rows / 2;           // safe u64 reads even if buffer is int32
    if (probe > 64) probe = 64;
    int is64 = 1;
    for (int i = 0; i < probe; ++i) {
        if (idx_as_u64[i] >= (1ULL << 31)) { is64 = 0; break; }
    }
    g_idx_is_i64 = is64;
}

__global__ void __launch_bounds__(256)
sparse_sgd_scatter(const float* __restrict__ grads,
                   const void* __restrict__ indices,
                   const float* __restrict__ lr_p,
                   float* __restrict__ out_w,
                   long long v_rows,
                   int vc,
                   int n_rows)
{
    int t    = blockIdx.x * blockDim.x + threadIdx.x;
    int row  = t >> 5;          // one warp per gradient row
    int lane = t & 31;          // one float4 (4 cols) per lane -> 128 cols
    if (row >= n_rows || row >= vc) return;

    long long widx;
    if (g_idx_is_i64)
        widx = __ldg((const long long*)indices + row);
    else
        widx = (long long)__ldg((const int*)indices + row);

    if (widx < 0 || widx >= v_rows) return;   // hard bounds guard

    float lr = __ldg(lr_p);
    const float4 g = *reinterpret_cast<const float4*>(
        grads + (size_t)row * EMB_D + lane * 4);

    float* dst = out_w + (size_t)widx * EMB_D + lane * 4;
    // no-return atomics (REDG path): duplicates accumulate correctly
    atomicAdd(dst + 0, -lr * g.x);
    atomicAdd(dst + 1, -lr * g.y);
    atomicAdd(dst + 2, -lr * g.z);
    atomicAdd(dst + 3, -lr * g.w);
}

extern "C" void kernel_launch(void* const* d_in, const int* in_sizes, int n_in,
                              void* d_out, int out_size)
{
    const float* grads   = (const float*)d_in[0];
    const float* weights = (const float*)d_in[1];
    const float* moments = (const float*)d_in[2];
    const void*  indices = d_in[3];
    const float* lr      = (const float*)d_in[4];

    size_t w_elems = (size_t)in_sizes[1];   // V*D
    size_t m_elems = (size_t)in_sizes[2];   // V*D
    int    n_rows  = in_sizes[3];           // N (padded gradient rows)
    long long v_rows = (long long)(w_elems / EMB_D);

    float* out_w = (float*)d_out;

    // 1) weights -> out (scatter below is stream-ordered after this)
    size_t w_copy = w_elems;
    if (w_copy > (size_t)out_size) w_copy = (size_t)out_size;
    cudaMemcpyAsync(out_w, weights, w_copy * sizeof(float),
                    cudaMemcpyDeviceToDevice, 0);

    // 2) moments pass-through (only if the output holds both tensors)
    if ((size_t)out_size >= w_elems + m_elems) {
        cudaMemcpyAsync(out_w + w_elems, moments, m_elems * sizeof(float),
                        cudaMemcpyDeviceToDevice, 0);
    }

    // 3) detect index width, then sparse scatter-add update
    detect_index_width<<<1, 1>>>((const unsigned long long*)indices, n_rows);

    long long total_threads = (long long)n_rows * 32;
    int block = 256;
    int grid  = (int)((total_threads + block - 1) / block);
    sparse_sgd_scatter<<<grid, block>>>(grads, indices, lr, out_w,
                                        v_rows, VALID_COUNT_DEFAULT, n_rows);
}

// round 3
// speedup vs baseline: 1.0794x; 1.0794x over previous
#include <cuda_runtime.h>
#include <cuda_bf16.h>
#include <stdint.h>

// HabanaOptimizerSparseSgd:
//   weights_out[indices[i]] -= lr * gradients[i]   for i < valid_count
//   moments_out = moments (pass-through copy)
//
// Inputs (metadata order):
//   d_in[0] gradients  [N, 128] float32
//   d_in[1] weights    [V, 128] float32
//   d_in[2] moments    [V, 128] float32
//   d_in[3] indices    [N]      declared int64; actually int32 on device
//                               (JAX x64 disabled) -> runtime width detect
//   d_in[4] learning_rate [1]   float32
// Output: concat(weights_out, moments_out) float32
//
// Structure (captured as a forked graph):
//   s0: weights memcpy ──e_w──> s1: detect + scatter ──e_s──┐
//   s0:                 moments memcpy (concurrent)  <──────┘ join

#define EMB_D 128
#define VALID_COUNT_DEFAULT 200000

// 1 = indices are 8-byte, 0 = indices are 4-byte
__device__ int g_idx_is_i64;

__global__ void detect_index_width(const unsigned long long* __restrict__ idx_as_u64,
                                   int n_rows)
{
    // int64 indices (< 2^31): every u64 word small. int32 indices: high half of
    // each u64 word is a random index in [0, 1M) -> nonzero within 64 samples.
    int probe = n_rows / 2;
    if (probe > 64) probe = 64;
    int is64 = 1;
    for (int i = 0; i < probe; ++i) {
        if (idx_as_u64[i] >= (1ULL << 31)) { is64 = 0; break; }
    }
    g_idx_is_i64 = is64;
}

__global__ void __launch_bounds__(256)
sparse_sgd_scatter(const float* __restrict__ grads,
                   const void* __restrict__ indices,
                   const float* __restrict__ lr_p,
                   float* __restrict__ out_w,
                   long long v_rows,
                   int n_valid)
{
    int t    = blockIdx.x * blockDim.x + threadIdx.x;
    int row  = t >> 5;          // one warp per valid gradient row
    int lane = t & 31;          // one float4 (4 cols) per lane -> 128 cols
    if (row >= n_valid) return;

    long long widx;
    if (g_idx_is_i64)
        widx = __ldg((const long long*)indices + row);
    else
        widx = (long long)__ldg((const int*)indices + row);

    if (widx < 0 || widx >= v_rows) return;   // hard bounds guard

    float lr = __ldg(lr_p);
    const float4 g = *reinterpret_cast<const float4*>(
        grads + (size_t)row * EMB_D + lane * 4);

    float* dst = out_w + (size_t)widx * EMB_D + lane * 4;
    float x = -lr * g.x, y = -lr * g.y, z = -lr * g.z, w = -lr * g.w;
    // one 16B no-return vector atomic (sm_90+): 4x fewer REDG dispatches
    asm volatile("red.global.add.v4.f32 [%0], {%1, %2, %3, %4};"
                 :: "l"(dst), "f"(x), "f"(y), "f"(z), "f"(w)
                 : "memory");
}

// Host-side objects created once at static-init (no device memory allocated).
static cudaStream_t g_s1;
static cudaEvent_t  g_e_w, g_e_s;
static bool         g_fork_ok = false;
static struct ForkInit {
    ForkInit() {
        bool ok = true;
        ok &= (cudaStreamCreateWithFlags(&g_s1, cudaStreamNonBlocking) == cudaSuccess);
        ok &= (cudaEventCreateWithFlags(&g_e_w, cudaEventDisableTiming) == cudaSuccess);
        ok &= (cudaEventCreateWithFlags(&g_e_s, cudaEventDisableTiming) == cudaSuccess);
        g_fork_ok = ok;
    }
} g_fork_init;

extern "C" void kernel_launch(void* const* d_in, const int* in_sizes, int n_in,
                              void* d_out, int out_size)
{
    const float* grads   = (const float*)d_in[0];
    const float* weights = (const float*)d_in[1];
    const float* moments = (const float*)d_in[2];
    const void*  indices = d_in[3];
    const float* lr      = (const float*)d_in[4];

    size_t w_elems = (size_t)in_sizes[1];   // V*D
    size_t m_elems = (size_t)in_sizes[2];   // V*D
    int    n_rows  = in_sizes[3];           // N (padded gradient rows)
    long long v_rows = (long long)(w_elems / EMB_D);

    int n_valid = VALID_COUNT_DEFAULT;
    if (n_valid > n_rows) n_valid = n_rows;

    float* out_w = (float*)d_out;

    size_t w_copy = w_elems;
    if (w_copy > (size_t)out_size) w_copy = (size_t)out_size;
    bool do_moments = ((size_t)out_size >= w_elems + m_elems);

    long long total_threads = (long long)n_valid * 32;
    int block = 256;
    int grid  = (int)((total_threads + block - 1) / block);

    if (g_fork_ok) {
        // s0: weights copy
        cudaMemcpyAsync(out_w, weights, w_copy * sizeof(float),
                        cudaMemcpyDeviceToDevice, 0);
        cudaEventRecord(g_e_w, 0);

        // s1: scatter, ordered after weights copy
        cudaStreamWaitEvent(g_s1, g_e_w, 0);
        detect_index_width<<<1, 1, 0, g_s1>>>(
            (const unsigned long long*)indices, n_rows);
        sparse_sgd_scatter<<<grid, block, 0, g_s1>>>(
            grads, indices, lr, out_w, v_rows, n_valid);
        cudaEventRecord(g_e_s, g_s1);

        // s0: moments copy runs concurrently with the scatter
        if (do_moments) {
            cudaMemcpyAsync(out_w + w_elems, moments, m_elems * sizeof(float),
                            cudaMemcpyDeviceToDevice, 0);
        }
        // join
        cudaStreamWaitEvent(0, g_e_s, 0);
    } else {
        // serial fallback
        cudaMemcpyAsync(out_w, weights, w_copy * sizeof(float),
                        cudaMemcpyDeviceToDevice, 0);
        if (do_moments) {
            cudaMemcpyAsync(out_w + w_elems, moments, m_elems * sizeof(float),
                            cudaMemcpyDeviceToDevice, 0);
        }
        detect_index_width<<<1, 1>>>((const unsigned long long*)indices, n_rows);
        sparse_sgd_scatter<<<grid, block>>>(grads, indices, lr, out_w,
                                            v_rows, n_valid);
    }
}

// round 4
// speedup vs baseline: 1.1464x; 1.0621x over previous
#include <cuda_runtime.h>
#include <cuda_bf16.h>
#include <stdint.h>

// HabanaOptimizerSparseSgd — inverted-scatter formulation:
//   Build per-weight-row linked lists of gradient rows, then a single fused
//   sweep computes weights_out = weights - lr * sum(listed grads) AND copies
//   moments, in one full-bandwidth pass. No atomics RMW on the 512B rows,
//   no separate memcpy passes.
//
// Inputs (metadata order):
//   d_in[0] gradients  [N, 128] float32
//   d_in[1] weights    [V, 128] float32
//   d_in[2] moments    [V, 128] float32
//   d_in[3] indices    [N]  declared int64; actually int32 (JAX x64 off)
//   d_in[4] learning_rate [1] float32
// Output: concat(weights_out, moments_out) float32

#define EMB_D 128
#define VALID_COUNT_DEFAULT 200000
#define HEADS_CAP 1000000      // V
#define NEXT_CAP  262144       // N

__device__ int g_idx_is_i64;
__device__ int g_heads[HEADS_CAP];
__device__ int g_next[NEXT_CAP];

// ---------------- index width detection (int32 vs int64 buffer) -----------
__global__ void detect_index_width(const unsigned long long* __restrict__ idx_as_u64,
                                   int n_rows)
{
    int probe = n_rows / 2;
    if (probe > 64) probe = 64;
    int is64 = 1;
    for (int i = 0; i < probe; ++i) {
        if (idx_as_u64[i] >= (1ULL << 31)) { is64 = 0; break; }
    }
    g_idx_is_i64 = is64;
}

// ---------------- phase 1: reset heads ------------------------------------
__global__ void __launch_bounds__(256)
reset_heads(int v_rows)
{
    int4 minus1 = make_int4(-1, -1, -1, -1);
    int stride = gridDim.x * blockDim.x;
    int n4 = v_rows >> 2;
    for (int i = blockIdx.x * blockDim.x + threadIdx.x; i < n4; i += stride)
        reinterpret_cast<int4*>(g_heads)[i] = minus1;
    // tail (v_rows not multiple of 4)
    int t = blockIdx.x * blockDim.x + threadIdx.x;
    int base = n4 << 2;
    if (t < (v_rows - base)) g_heads[base + t] = -1;
}

// ---------------- phase 2: build linked lists ------------------------------
__global__ void __launch_bounds__(256)
build_lists(const void* __restrict__ indices, int n_valid, long long v_rows)
{
    int i = blockIdx.x * blockDim.x + threadIdx.x;
    if (i >= n_valid) return;
    long long widx = g_idx_is_i64 ? __ldg((const long long*)indices + i)
                                  : (long long)__ldg((const int*)indices + i);
    if (widx < 0 || widx >= v_rows) return;     // drop invalid (bounds guard)
    int old = atomicExch(&g_heads[(int)widx], i);
    g_next[i] = old;
}

// ---------------- phase 3: fused sweep (weights update + moments copy) -----
// blocks [0, wblocks): 8 warps/block, warp per weight row.
// blocks [wblocks, gridDim.x): flat float4 copy of moments.
__global__ void __launch_bounds__(256)
fused_sweep(const float*  __restrict__ weights,
            const float*  __restrict__ grads,
            const float*  __restrict__ moments,
            const float*  __restrict__ lr_p,
            float*        __restrict__ out,       // [V*128 weights][V*128 moments]
            long long v_rows,
            size_t w_elems,
            size_t m_elems,
            int wblocks)
{
    if (blockIdx.x < (unsigned)wblocks) {
        // ---- weights part: one warp per vocab row ----
        int warp = (blockIdx.x << 3) | (threadIdx.x >> 5);   // 8 warps/block
        int lane = threadIdx.x & 31;
        if (warp >= v_rows) return;

        const float4 w = *reinterpret_cast<const float4*>(
            weights + (size_t)warp * EMB_D + lane * 4);
        float4 acc = make_float4(0.f, 0.f, 0.f, 0.f);

        int node = g_heads[warp];
        if (node >= 0) {
            float lr = __ldg(lr_p);
            do {
                const float4 g = *reinterpret_cast<const float4*>(
                    grads + (size_t)node * EMB_D + lane * 4);
                acc.x += g.x; acc.y += g.y; acc.z += g.z; acc.w += g.w;
                node = g_next[node];
            } while (node >= 0);
            acc.x *= -lr; acc.y *= -lr; acc.z *= -lr; acc.w *= -lr;
        }

        float4 r = make_float4(w.x + acc.x, w.y + acc.y,
                               w.z + acc.z, w.w + acc.w);
        *reinterpret_cast<float4*>(out + (size_t)warp * EMB_D + lane * 4) = r;
    } else {
        // ---- moments part: flat float4 grid-stride copy ----
        size_t n4 = m_elems >> 2;
        const float4* src = reinterpret_cast<const float4*>(moments);
        float4*       dst = reinterpret_cast<float4*>(out + w_elems);
        size_t stride = (size_t)(gridDim.x - wblocks) * blockDim.x;
        for (size_t i = (size_t)(blockIdx.x - wblocks) * blockDim.x + threadIdx.x;
             i < n4; i += stride)
            dst[i] = src[i];
    }
}

// ---------------- fallback path (R3: memcpy + vector atomics) --------------
__global__ void __launch_bounds__(256)
sparse_sgd_scatter(const float* __restrict__ grads,
                   const void* __restrict__ indices,
                   const float* __restrict__ lr_p,
                   float* __restrict__ out_w,
                   long long v_rows,
                   int n_valid)
{
    int t    = blockIdx.x * blockDim.x + threadIdx.x;
    int row  = t >> 5;
    int lane = t & 31;
    if (row >= n_valid) return;

    long long widx = g_idx_is_i64 ? __ldg((const long long*)indices + row)
                                  : (long long)__ldg((const int*)indices + row);
    if (widx < 0 || widx >= v_rows) return;

    float lr = __ldg(lr_p);
    const float4 g = *reinterpret_cast<const float4*>(
        grads + (size_t)row * EMB_D + lane * 4);
    float* dst = out_w + (size_t)widx * EMB_D + lane * 4;
    float x = -lr * g.x, y = -lr * g.y, z = -lr * g.z, w = -lr * g.w;
    asm volatile("red.global.add.v4.f32 [%0], {%1, %2, %3, %4};"
                 :: "l"(dst), "f"(x), "f"(y), "f"(z), "f"(w)
                 : "memory");
}

extern "C" void kernel_launch(void* const* d_in, const int* in_sizes, int n_in,
                              void* d_out, int out_size)
{
    const float* grads   = (const float*)d_in[0];
    const float* weights = (const float*)d_in[1];
    const float* moments = (const float*)d_in[2];
    const void*  indices = d_in[3];
    const float* lr      = (const float*)d_in[4];

    size_t w_elems = (size_t)in_sizes[1];
    size_t m_elems = (size_t)in_sizes[2];
    int    n_rows  = in_sizes[3];
    long long v_rows = (long long)(w_elems / EMB_D);

    int n_valid = VALID_COUNT_DEFAULT;
    if (n_valid > n_rows) n_valid = n_rows;

    float* out_w = (float*)d_out;
    bool do_moments = ((size_t)out_size >= w_elems + m_elems);

    detect_index_width<<<1, 1>>>((const unsigned long long*)indices, n_rows);

    if (v_rows <= HEADS_CAP && n_valid <= NEXT_CAP && do_moments) {
        // ---- fast path: inverted scatter, single fused sweep ----
        reset_heads<<<512, 256>>>((int)v_rows);
        build_lists<<<(n_valid + 255) / 256, 256>>>(indices, n_valid, v_rows);

        int wblocks = (int)((v_rows + 7) / 8);      // 8 rows per block
        int mblocks = 16384;                        // moments copy blocks
        fused_sweep<<<wblocks + mblocks, 256>>>(
            weights, grads, moments, lr, out_w,
            v_rows, w_elems, m_elems, wblocks);
    } else {
        // ---- fallback: copies + vector-atomic scatter ----
        size_t w_copy = w_elems;
        if (w_copy > (size_t)out_size) w_copy = (size_t)out_size;
        cudaMemcpyAsync(out_w, weights, w_copy * sizeof(float),
                        cudaMemcpyDeviceToDevice, 0);
        if (do_moments)
            cudaMemcpyAsync(out_w + w_elems, moments, m_elems * sizeof(float),
                            cudaMemcpyDeviceToDevice, 0);
        long long total_threads = (long long)n_valid * 32;
        int grid = (int)((total_threads + 255) / 256);
        sparse_sgd_scatter<<<grid, 256>>>(grads, indices, lr, out_w,
                                          v_rows, n_valid);
    }
}

// round 5
// speedup vs baseline: 1.2046x; 1.0508x over previous
#include <cuda_runtime.h>
#include <cuda_bf16.h>
#include <stdint.h>

// HabanaOptimizerSparseSgd — inverted-scatter, 2-kernel formulation:
//   K1 build:  per-weight-row linked lists via atomicExch (heads encoded as
//              node+1, 0 = empty; index dtype self-detected per block).
//   K2 sweep:  warp per vocab row: weights_out = w - lr * sum(listed grads),
//              moments_out = m, and heads[row] reset to 0 for the next call.
//              Single full-bandwidth pass; no RMW atomics on 512B rows.
//
// heads[] is zero-initialized at module load and re-zeroed by every sweep,
// so each kernel_launch call sees a clean table (deterministic across the
// correctness run and all graph replays).
//
// Inputs (metadata order):
//   d_in[0] gradients  [N, 128] float32
//   d_in[1] weights    [V, 128] float32
//   d_in[2] moments    [V, 128] float32
//   d_in[3] indices    [N]  declared int64; actually int32 (JAX x64 off)
//   d_in[4] learning_rate [1] float32
// Output: concat(weights_out, moments_out) float32

#define EMB_D 128
#define VALID_COUNT_DEFAULT 200000
#define HEADS_CAP 1000000      // V
#define NEXT_CAP  262144       // N

__device__ int g_heads[HEADS_CAP];   // 0 = empty, else node+1
__device__ int g_next[NEXT_CAP];     // 0 = end,   else node+1
__device__ int g_idx_is_i64;         // used by fallback path only

// ---------------- K1: build linked lists (detection inlined) ---------------
__global__ void __launch_bounds__(256)
build_lists(const void* __restrict__ indices, int n_valid, int n_rows,
            long long v_rows)
{
    __shared__ int s_is64;
    if (threadIdx.x == 0) {
        // int64 indices (< 2^31): every u64 word small. int32 indices: high
        // half of each u64 word is a random index -> nonzero within 64 words.
        const unsigned long long* u = (const unsigned long long*)indices;
        int probe = n_rows / 2; if (probe > 64) probe = 64;
        int is64 = 1;
        for (int i = 0; i < probe; ++i)
            if (u[i] >= (1ULL << 31)) { is64 = 0; break; }
        s_is64 = is64;
    }
    __syncthreads();

    int i = blockIdx.x * blockDim.x + threadIdx.x;
    if (i >= n_valid) return;
    long long widx = s_is64 ? __ldg((const long long*)indices + i)
                            : (long long)__ldg((const int*)indices + i);
    if (widx < 0 || widx >= v_rows) return;      // bounds guard
    int old = atomicExch(&g_heads[(int)widx], i + 1);
    g_next[i] = old;
}

// ---------------- K2: fused sweep ------------------------------------------
// One warp per vocab row: weights update + moments copy + head reset.
__global__ void __launch_bounds__(256)
fused_sweep(const float*  __restrict__ weights,
            const float*  __restrict__ grads,
            const float*  __restrict__ moments,
            const float*  __restrict__ lr_p,
            float*        __restrict__ out,   // [V*128 weights][V*128 moments]
            long long v_rows,
            size_t w_elems)
{
    long long row = ((long long)blockIdx.x << 3) | (threadIdx.x >> 5);
    int lane = threadIdx.x & 31;
    if (row >= v_rows) return;

    size_t off = (size_t)row * EMB_D + lane * 4;

    const float4 w = __ldcs(reinterpret_cast<const float4*>(weights + off));
    const float4 m = __ldcs(reinterpret_cast<const float4*>(moments + off));

    int node = g_heads[row];                 // broadcast load per warp
    float4 r = w;
    if (node > 0) {
        if (lane == 0) g_heads[row] = 0;     // self-reset for next call
        float lr = __ldg(lr_p);
        float4 acc = make_float4(0.f, 0.f, 0.f, 0.f);
        do {
            const float4 g = __ldcs(reinterpret_cast<const float4*>(
                grads + (size_t)(node - 1) * EMB_D + lane * 4));
            acc.x += g.x; acc.y += g.y; acc.z += g.z; acc.w += g.w;
            node = g_next[node - 1];
        } while (node > 0);
        r.x = w.x - lr * acc.x;
        r.y = w.y - lr * acc.y;
        r.z = w.z - lr * acc.z;
        r.w = w.w - lr * acc.w;
    }

    __stcs(reinterpret_cast<float4*>(out + off), r);
    __stcs(reinterpret_cast<float4*>(out + w_elems + off), m);
}

// ---------------- fallback path (memcpy + vector atomics) ------------------
__global__ void detect_index_width(const unsigned long long* __restrict__ u,
                                   int n_rows)
{
    int probe = n_rows / 2; if (probe > 64) probe = 64;
    int is64 = 1;
    for (int i = 0; i < probe; ++i)
        if (u[i] >= (1ULL << 31)) { is64 = 0; break; }
    g_idx_is_i64 = is64;
}

__global__ void __launch_bounds__(256)
sparse_sgd_scatter(const float* __restrict__ grads,
                   const void* __restrict__ indices,
                   const float* __restrict__ lr_p,
                   float* __restrict__ out_w,
                   long long v_rows,
                   int n_valid)
{
    int t    = blockIdx.x * blockDim.x + threadIdx.x;
    int row  = t >> 5;
    int lane = t & 31;
    if (row >= n_valid) return;

    long long widx = g_idx_is_i64 ? __ldg((const long long*)indices + row)
                                  : (long long)__ldg((const int*)indices + row);
    if (widx < 0 || widx >= v_rows) return;

    float lr = __ldg(lr_p);
    const float4 g = *reinterpret_cast<const float4*>(
        grads + (size_t)row * EMB_D + lane * 4);
    float* dst = out_w + (size_t)widx * EMB_D + lane * 4;
    float x = -lr * g.x, y = -lr * g.y, z = -lr * g.z, w = -lr * g.w;
    asm volatile("red.global.add.v4.f32 [%0], {%1, %2, %3, %4};"
                 :: "l"(dst), "f"(x), "f"(y), "f"(z), "f"(w)
                 : "memory");
}

extern "C" void kernel_launch(void* const* d_in, const int* in_sizes, int n_in,
                              void* d_out, int out_size)
{
    const float* grads   = (const float*)d_in[0];
    const float* weights = (const float*)d_in[1];
    const float* moments = (const float*)d_in[2];
    const void*  indices = d_in[3];
    const float* lr      = (const float*)d_in[4];

    size_t w_elems = (size_t)in_sizes[1];
    size_t m_elems = (size_t)in_sizes[2];
    int    n_rows  = in_sizes[3];
    long long v_rows = (long long)(w_elems / EMB_D);

    int n_valid = VALID_COUNT_DEFAULT;
    if (n_valid > n_rows) n_valid = n_rows;

    float* out_w = (float*)d_out;
    bool do_moments = ((size_t)out_size >= w_elems + m_elems);

    if (v_rows <= HEADS_CAP && n_valid <= NEXT_CAP && do_moments &&
        m_elems == w_elems) {
        // ---- fast path: build lists, then single fused sweep ----
        build_lists<<<(n_valid + 255) / 256, 256>>>(indices, n_valid,
                                                    n_rows, v_rows);
        int wblocks = (int)((v_rows + 7) / 8);   // 8 rows (warps) per block
        fused_sweep<<<wblocks, 256>>>(weights, grads, moments, lr, out_w,
                                      v_rows, w_elems);
    } else {
        // ---- fallback: copies + vector-atomic scatter ----
        size_t w_copy = w_elems;
        if (w_copy > (size_t)out_size) w_copy = (size_t)out_size;
        cudaMemcpyAsync(out_w, weights, w_copy * sizeof(float),
                        cudaMemcpyDeviceToDevice, 0);
        if (do_moments)
            cudaMemcpyAsync(out_w + w_elems, moments, m_elems * sizeof(float),
                            cudaMemcpyDeviceToDevice, 0);
        detect_index_width<<<1, 1>>>((const unsigned long long*)indices, n_rows);
        long long total_threads = (long long)n_valid * 32;
        int grid = (int)((total_threads + 255) / 256);
        sparse_sgd_scatter<<<grid, 256>>>(grads, indices, lr, out_w,
                                          v_rows, n_valid);
    }
}